// round 1
// baseline (speedup 1.0000x reference)
#include <cuda_runtime.h>

#define BB    4
#define NPER  100000
#define NSOL  8
#define NROWS (BB * NPER)
#define NBINS (BB * NSOL)

// ---------------- device-global accumulators (no allocs allowed) -------------
__device__ float g_ae[NBINS];   // a_energy[b][s]
__device__ float g_ld[NBINS];   // load[b][s]
__device__ float g_vol[BB];     // vol[b]
__device__ int   g_is64;        // 1 if A_ind is int64, 0 if int32

// ---------------- helpers ----------------------------------------------------
__device__ __forceinline__ void warp_reduce_add(float& v) {
#pragma unroll
    for (int off = 16; off > 0; off >>= 1)
        v += __shfl_xor_sync(0xffffffffu, v, off);
}

__device__ __forceinline__ void accum_row(float (&acc)[BB][NSOL], int r, const float* t) {
    if (r < NPER) {
#pragma unroll
        for (int s = 0; s < NSOL; s++) acc[0][s] += t[s];
    } else if (r < 2 * NPER) {
#pragma unroll
        for (int s = 0; s < NSOL; s++) acc[1][s] += t[s];
    } else if (r < 3 * NPER) {
#pragma unroll
        for (int s = 0; s < NSOL; s++) acc[2][s] += t[s];
    } else {
#pragma unroll
        for (int s = 0; s < NSOL; s++) acc[3][s] += t[s];
    }
}

// ---------------- kernel 0a: detect index dtype ------------------------------
// If the buffer really holds int64 indices (< 2^32, positive), every odd 32-bit
// word of the first 32 entries is 0. For real int32 data the probability of
// that is ~(2.5e-6)^32.
__global__ void detect_kernel(const int* __restrict__ ind32) {
    if (threadIdx.x == 0) {
        int all0 = 1;
        for (int k = 0; k < 32; k++)
            if (ind32[2 * k + 1] != 0) all0 = 0;
        g_is64 = all0;
    }
}

// ---------------- kernel 0b: zero accumulators -------------------------------
__global__ void init_kernel() {
    int t = threadIdx.x;
    if (t < NBINS) { g_ae[t] = 0.0f; g_ld[t] = 0.0f; }
    if (t < BB)    g_vol[t] = 0.0f;
}

// ---------------- kernel 1: per-nnz energy accumulation ----------------------
// a_energy[row/NPER][s] += A_val * x[row][s] * x[col][s]
template <typename IT>
__device__ __forceinline__ void spmv_loop(const IT* __restrict__ rows,
                                          const IT* __restrict__ cols,
                                          const float* __restrict__ val,
                                          const float4* __restrict__ x4,
                                          int nnz, int i0, int stride,
                                          float (&acc)[BB][NSOL]) {
    int i = i0;
    for (; i + stride < nnz; i += 2 * stride) {
        int   r0 = (int)rows[i];
        int   c0 = (int)cols[i];
        float v0 = val[i];
        int   r1 = (int)rows[i + stride];
        int   c1 = (int)cols[i + stride];
        float v1 = val[i + stride];

        float4 A0 = __ldg(x4 + 2 * r0), A1 = __ldg(x4 + 2 * r0 + 1);
        float4 B0 = __ldg(x4 + 2 * c0), B1 = __ldg(x4 + 2 * c0 + 1);
        float4 C0 = __ldg(x4 + 2 * r1), C1 = __ldg(x4 + 2 * r1 + 1);
        float4 D0 = __ldg(x4 + 2 * c1), D1 = __ldg(x4 + 2 * c1 + 1);

        float t0[NSOL] = { v0 * A0.x * B0.x, v0 * A0.y * B0.y,
                           v0 * A0.z * B0.z, v0 * A0.w * B0.w,
                           v0 * A1.x * B1.x, v0 * A1.y * B1.y,
                           v0 * A1.z * B1.z, v0 * A1.w * B1.w };
        accum_row(acc, r0, t0);

        float t1[NSOL] = { v1 * C0.x * D0.x, v1 * C0.y * D0.y,
                           v1 * C0.z * D0.z, v1 * C0.w * D0.w,
                           v1 * C1.x * D1.x, v1 * C1.y * D1.y,
                           v1 * C1.z * D1.z, v1 * C1.w * D1.w };
        accum_row(acc, r1, t1);
    }
    if (i < nnz) {
        int   r = (int)rows[i];
        int   c = (int)cols[i];
        float v = val[i];
        float4 A0 = __ldg(x4 + 2 * r), A1 = __ldg(x4 + 2 * r + 1);
        float4 B0 = __ldg(x4 + 2 * c), B1 = __ldg(x4 + 2 * c + 1);
        float t[NSOL] = { v * A0.x * B0.x, v * A0.y * B0.y,
                          v * A0.z * B0.z, v * A0.w * B0.w,
                          v * A1.x * B1.x, v * A1.y * B1.y,
                          v * A1.z * B1.z, v * A1.w * B1.w };
        accum_row(acc, r, t);
    }
}

__global__ void __launch_bounds__(256)
spmv_energy_kernel(const void* __restrict__ ind_base,
                   const float* __restrict__ val,
                   const float4* __restrict__ x4,
                   int nnz) {
    float acc[BB][NSOL];
#pragma unroll
    for (int b = 0; b < BB; b++)
#pragma unroll
        for (int s = 0; s < NSOL; s++) acc[b][s] = 0.0f;

    const int stride = gridDim.x * blockDim.x;
    const int i0     = blockIdx.x * blockDim.x + threadIdx.x;

    if (g_is64) {
        const long long* rows = (const long long*)ind_base;
        spmv_loop(rows, rows + nnz, val, x4, nnz, i0, stride, acc);
    } else {
        const int* rows = (const int*)ind_base;
        spmv_loop(rows, rows + nnz, val, x4, nnz, i0, stride, acc);
    }

    // thread -> warp -> block -> global reduction
#pragma unroll
    for (int b = 0; b < BB; b++)
#pragma unroll
        for (int s = 0; s < NSOL; s++) warp_reduce_add(acc[b][s]);

    __shared__ float sbin[NBINS];
    if (threadIdx.x < NBINS) sbin[threadIdx.x] = 0.0f;
    __syncthreads();
    if ((threadIdx.x & 31) == 0) {
#pragma unroll
        for (int b = 0; b < BB; b++)
#pragma unroll
            for (int s = 0; s < NSOL; s++)
                atomicAdd(&sbin[b * NSOL + s], acc[b][s]);
    }
    __syncthreads();
    if (threadIdx.x < NBINS) atomicAdd(&g_ae[threadIdx.x], sbin[threadIdx.x]);
}

// ---------------- kernel 2: row stats (load, vol) ----------------------------
__global__ void __launch_bounds__(256)
rowstats_kernel(const float4* __restrict__ x4,
                const float4* __restrict__ rhs4,
                const float* __restrict__ mass) {
    float acc[BB][NSOL];
    float accv[BB];
#pragma unroll
    for (int b = 0; b < BB; b++) {
        accv[b] = 0.0f;
#pragma unroll
        for (int s = 0; s < NSOL; s++) acc[b][s] = 0.0f;
    }

    const int stride = gridDim.x * blockDim.x;
    for (int i = blockIdx.x * blockDim.x + threadIdx.x; i < NROWS; i += stride) {
        float  m  = __ldg(mass + i);
        float4 x0 = __ldg(x4 + 2 * i),  x1 = __ldg(x4 + 2 * i + 1);
        float4 r0 = __ldg(rhs4 + 2 * i), r1 = __ldg(rhs4 + 2 * i + 1);
        float t[NSOL] = { m * r0.x * x0.x, m * r0.y * x0.y,
                          m * r0.z * x0.z, m * r0.w * x0.w,
                          m * r1.x * x1.x, m * r1.y * x1.y,
                          m * r1.z * x1.z, m * r1.w * x1.w };
        if (i < NPER) {
#pragma unroll
            for (int s = 0; s < NSOL; s++) acc[0][s] += t[s];
            accv[0] += m;
        } else if (i < 2 * NPER) {
#pragma unroll
            for (int s = 0; s < NSOL; s++) acc[1][s] += t[s];
            accv[1] += m;
        } else if (i < 3 * NPER) {
#pragma unroll
            for (int s = 0; s < NSOL; s++) acc[2][s] += t[s];
            accv[2] += m;
        } else {
#pragma unroll
            for (int s = 0; s < NSOL; s++) acc[3][s] += t[s];
            accv[3] += m;
        }
    }

#pragma unroll
    for (int b = 0; b < BB; b++) {
#pragma unroll
        for (int s = 0; s < NSOL; s++) warp_reduce_add(acc[b][s]);
        warp_reduce_add(accv[b]);
    }

    __shared__ float sbin[NBINS + BB];
    if (threadIdx.x < NBINS + BB) sbin[threadIdx.x] = 0.0f;
    __syncthreads();
    if ((threadIdx.x & 31) == 0) {
#pragma unroll
        for (int b = 0; b < BB; b++) {
#pragma unroll
            for (int s = 0; s < NSOL; s++)
                atomicAdd(&sbin[b * NSOL + s], acc[b][s]);
            atomicAdd(&sbin[NBINS + b], accv[b]);
        }
    }
    __syncthreads();
    if (threadIdx.x < NBINS) atomicAdd(&g_ld[threadIdx.x], sbin[threadIdx.x]);
    else if (threadIdx.x < NBINS + BB)
        atomicAdd(&g_vol[threadIdx.x - NBINS], sbin[threadIdx.x]);
}

// ---------------- kernel 3: finalize scalar ----------------------------------
__global__ void finalize_kernel(float* __restrict__ out) {
    int t = threadIdx.x;  // 32 threads, one per (b, s)
    int b = t / NSOL;
    float ae  = g_ae[t];
    float ld  = g_ld[t];
    float vol = g_vol[b];

    float sigma  = ld / fmaxf(ae, 1e-4f);
    float kkt_e  = (0.5f * ae * sigma - ld) * sigma / vol;
    float comp_b = sigma * ld / vol;

    warp_reduce_add(kkt_e);
    warp_reduce_add(comp_b);

    if (t == 0) {
        float kkt  = kkt_e / (float)NBINS;
        float comp = -(comp_b / (float)NBINS);
        out[0] = 0.5f * comp + 0.5f * kkt;   // LAMB_COMP = 0.5
    }
}

// ---------------- launch ------------------------------------------------------
extern "C" void kernel_launch(void* const* d_in, const int* in_sizes, int n_in,
                              void* d_out, int out_size) {
    const float* x     = (const float*)d_in[0];
    const float* rhs   = (const float*)d_in[1];
    const void*  A_ind = d_in[2];
    const float* A_val = (const float*)d_in[3];
    // d_in[4] (subspace_vectors) is unused by the reference
    const float* mass  = (const float*)d_in[5];
    const int    nnz   = in_sizes[3];

    detect_kernel<<<1, 32>>>((const int*)A_ind);
    init_kernel<<<1, 64>>>();
    spmv_energy_kernel<<<1480, 256>>>(A_ind, A_val, (const float4*)x, nnz);
    rowstats_kernel<<<512, 256>>>((const float4*)x, (const float4*)rhs, mass);
    finalize_kernel<<<1, 32>>>((float*)d_out);
}

// round 2
// speedup vs baseline: 1.3037x; 1.3037x over previous
#include <cuda_runtime.h>

#define BB    4
#define NPER  100000
#define NSOL  8
#define NROWS (BB * NPER)
#define NBINS (BB * NSOL)

// ---------------- device-global accumulators (no allocs allowed) -------------
__device__ float g_ae[NBINS];   // a_energy[b][s]
__device__ float g_ld[NBINS];   // load[b][s]
__device__ float g_vol[BB];     // vol[b]
__device__ int   g_is64;        // 1 if A_ind is int64, 0 if int32

// ---------------- helpers ----------------------------------------------------
__device__ __forceinline__ void warp_reduce_add(float& v) {
#pragma unroll
    for (int off = 16; off > 0; off >>= 1)
        v += __shfl_xor_sync(0xffffffffu, v, off);
}

// Reduce across lanes of the SAME parity only (offsets 16,8,4,2).
__device__ __forceinline__ void warp_reduce_add_pair(float& v) {
#pragma unroll
    for (int off = 16; off >= 2; off >>= 1)
        v += __shfl_xor_sync(0xffffffffu, v, off);
}

// Static-index compare-chain accumulate of a 4-sol partial into the right batch.
__device__ __forceinline__ void accum4(float (&acc)[BB][4], int r, float tx, float ty,
                                       float tz, float tw) {
    if (r < 2 * NPER) {
        if (r < NPER) { acc[0][0] += tx; acc[0][1] += ty; acc[0][2] += tz; acc[0][3] += tw; }
        else          { acc[1][0] += tx; acc[1][1] += ty; acc[1][2] += tz; acc[1][3] += tw; }
    } else {
        if (r < 3 * NPER) { acc[2][0] += tx; acc[2][1] += ty; acc[2][2] += tz; acc[2][3] += tw; }
        else              { acc[3][0] += tx; acc[3][1] += ty; acc[3][2] += tz; acc[3][3] += tw; }
    }
}

// ---------------- kernel 0: detect index dtype + zero accumulators -----------
// If the buffer holds int64 indices (< 2^32, nonneg), every odd 32-bit word of
// the first 32 entries is 0. For real int32 data P(all zero) ~ (2.5e-6)^32.
__global__ void init_kernel(const int* __restrict__ ind32) {
    int t = threadIdx.x;
    if (t == 0) {
        int all0 = 1;
        for (int k = 0; k < 32; k++)
            if (ind32[2 * k + 1] != 0) all0 = 0;
        g_is64 = all0;
    }
    if (t < NBINS) { g_ae[t] = 0.0f; g_ld[t] = 0.0f; }
    if (t < BB)    g_vol[t] = 0.0f;
}

// ---------------- kernel 1: per-nnz energy accumulation ----------------------
// Lane pairs share one nnz: even lane handles sols 0-3 (x4[2r]), odd lane
// sols 4-7 (x4[2r+1]). Both halves of a row live in the SAME 128B line, so the
// L1 coalescer merges them -> 2 wavefronts per nnz (the floor) instead of 4.
template <typename IT>
__device__ __forceinline__ void spmv_loop(const IT* __restrict__ rows,
                                          const IT* __restrict__ cols,
                                          const float* __restrict__ val,
                                          const float4* __restrict__ x4,
                                          int nnz, int p0, int pstride, int half,
                                          float (&acc)[BB][4]) {
    int i = p0;
    for (; i + pstride < nnz; i += 2 * pstride) {
        const int j = i + pstride;
        int   r0 = (int)rows[i];
        int   c0 = (int)cols[i];
        float v0 = val[i];
        int   r1 = (int)rows[j];
        int   c1 = (int)cols[j];
        float v1 = val[j];

        float4 a = __ldg(x4 + 2 * r0 + half);
        float4 b = __ldg(x4 + 2 * c0 + half);
        float4 c = __ldg(x4 + 2 * r1 + half);
        float4 d = __ldg(x4 + 2 * c1 + half);

        accum4(acc, r0, v0 * a.x * b.x, v0 * a.y * b.y, v0 * a.z * b.z, v0 * a.w * b.w);
        accum4(acc, r1, v1 * c.x * d.x, v1 * c.y * d.y, v1 * c.z * d.z, v1 * c.w * d.w);
    }
    if (i < nnz) {
        int   r = (int)rows[i];
        int   c = (int)cols[i];
        float v = val[i];
        float4 a = __ldg(x4 + 2 * r + half);
        float4 b = __ldg(x4 + 2 * c + half);
        accum4(acc, r, v * a.x * b.x, v * a.y * b.y, v * a.z * b.z, v * a.w * b.w);
    }
}

__global__ void __launch_bounds__(256)
spmv_energy_kernel(const void* __restrict__ ind_base,
                   const float* __restrict__ val,
                   const float4* __restrict__ x4,
                   int nnz) {
    float acc[BB][4];
#pragma unroll
    for (int b = 0; b < BB; b++)
#pragma unroll
        for (int s = 0; s < 4; s++) acc[b][s] = 0.0f;

    const int g       = blockIdx.x * blockDim.x + threadIdx.x;
    const int half    = g & 1;                       // == lane parity (blockDim even)
    const int p0      = g >> 1;
    const int pstride = (gridDim.x * blockDim.x) >> 1;

    if (g_is64) {
        const long long* rows = (const long long*)ind_base;
        spmv_loop(rows, rows + nnz, val, x4, nnz, p0, pstride, half, acc);
    } else {
        const int* rows = (const int*)ind_base;
        spmv_loop(rows, rows + nnz, val, x4, nnz, p0, pstride, half, acc);
    }

    // Same-parity warp reduction: after this, lane 0 holds sols 0-3 sums,
    // lane 1 holds sols 4-7 sums (per batch).
#pragma unroll
    for (int b = 0; b < BB; b++)
#pragma unroll
        for (int s = 0; s < 4; s++) warp_reduce_add_pair(acc[b][s]);

    __shared__ float sbin[NBINS];
    if (threadIdx.x < NBINS) sbin[threadIdx.x] = 0.0f;
    __syncthreads();
    const int lane = threadIdx.x & 31;
    if (lane < 2) {
#pragma unroll
        for (int b = 0; b < BB; b++)
#pragma unroll
            for (int s = 0; s < 4; s++)
                atomicAdd(&sbin[b * NSOL + lane * 4 + s], acc[b][s]);
    }
    __syncthreads();
    if (threadIdx.x < NBINS) atomicAdd(&g_ae[threadIdx.x], sbin[threadIdx.x]);
}

// ---------------- kernel 2: row stats (load, vol) ----------------------------
// One row per thread. Warps almost never straddle a batch boundary, so the
// common path is a 9-value same-bin warp reduction.
__global__ void __launch_bounds__(256)
rowstats_kernel(const float4* __restrict__ x4,
                const float4* __restrict__ rhs4,
                const float* __restrict__ mass) {
    const int i    = blockIdx.x * blockDim.x + threadIdx.x;
    const int lane = threadIdx.x & 31;

    float t[NSOL] = {0, 0, 0, 0, 0, 0, 0, 0};
    float m = 0.0f;
    int   b = 0;
    if (i < NROWS) {
        m = __ldg(mass + i);
        float4 x0 = __ldg(x4 + 2 * i),   x1 = __ldg(x4 + 2 * i + 1);
        float4 r0 = __ldg(rhs4 + 2 * i), r1 = __ldg(rhs4 + 2 * i + 1);
        t[0] = m * r0.x * x0.x;  t[1] = m * r0.y * x0.y;
        t[2] = m * r0.z * x0.z;  t[3] = m * r0.w * x0.w;
        t[4] = m * r1.x * x1.x;  t[5] = m * r1.y * x1.y;
        t[6] = m * r1.z * x1.z;  t[7] = m * r1.w * x1.w;
        b = (i >= NPER) + (i >= 2 * NPER) + (i >= 3 * NPER);
    }

    __shared__ float sbin[NBINS + BB];
    if (threadIdx.x < NBINS + BB) sbin[threadIdx.x] = 0.0f;
    __syncthreads();

    const int b0 = __shfl_sync(0xffffffffu, b, 0);
    if (__all_sync(0xffffffffu, b == b0)) {
        // fast path: whole warp in one batch
#pragma unroll
        for (int s = 0; s < NSOL; s++) warp_reduce_add(t[s]);
        warp_reduce_add(m);
        if (lane == 0) {
#pragma unroll
            for (int s = 0; s < NSOL; s++) atomicAdd(&sbin[b0 * NSOL + s], t[s]);
            atomicAdd(&sbin[NBINS + b0], m);
        }
    } else {
        // rare path: warp straddles a batch boundary (3 warps out of 12500)
#pragma unroll
        for (int s = 0; s < NSOL; s++) atomicAdd(&sbin[b * NSOL + s], t[s]);
        atomicAdd(&sbin[NBINS + b], m);
    }
    __syncthreads();
    if (threadIdx.x < NBINS) atomicAdd(&g_ld[threadIdx.x], sbin[threadIdx.x]);
    else if (threadIdx.x < NBINS + BB)
        atomicAdd(&g_vol[threadIdx.x - NBINS], sbin[threadIdx.x]);
}

// ---------------- kernel 3: finalize scalar ----------------------------------
__global__ void finalize_kernel(float* __restrict__ out) {
    int t = threadIdx.x;  // 32 threads, one per (b, s)
    int b = t / NSOL;
    float ae  = g_ae[t];
    float ld  = g_ld[t];
    float vol = g_vol[b];

    float sigma  = ld / fmaxf(ae, 1e-4f);
    float kkt_e  = (0.5f * ae * sigma - ld) * sigma / vol;
    float comp_b = sigma * ld / vol;

    warp_reduce_add(kkt_e);
    warp_reduce_add(comp_b);

    if (t == 0) {
        float kkt  = kkt_e / (float)NBINS;
        float comp = -(comp_b / (float)NBINS);
        out[0] = 0.5f * comp + 0.5f * kkt;   // LAMB_COMP = 0.5
    }
}

// ---------------- launch ------------------------------------------------------
extern "C" void kernel_launch(void* const* d_in, const int* in_sizes, int n_in,
                              void* d_out, int out_size) {
    const float* x     = (const float*)d_in[0];
    const float* rhs   = (const float*)d_in[1];
    const void*  A_ind = d_in[2];
    const float* A_val = (const float*)d_in[3];
    // d_in[4] (subspace_vectors) is unused by the reference
    const float* mass  = (const float*)d_in[5];
    const int    nnz   = in_sizes[3];

    init_kernel<<<1, 64>>>((const int*)A_ind);
    spmv_energy_kernel<<<1480, 256>>>(A_ind, A_val, (const float4*)x, nnz);
    rowstats_kernel<<<(NROWS + 255) / 256, 256>>>((const float4*)x, (const float4*)rhs, mass);
    finalize_kernel<<<1, 32>>>((float*)d_out);
}